// round 13
// baseline (speedup 1.0000x reference)
#include <cuda_runtime.h>
#include <cooperative_groups.h>
#include <math.h>

namespace cg = cooperative_groups;

#define BATCH 8
#define HH 720
#define WW 1280
#define HW (HH * WW)
#define NPIX (BATCH * HW)

#define CB 2                       // batches per chunk
#define NCHUNK (BATCH / CB)        // 4
#define CHUNK_PIX (CB * HW)        // 1,843,200

#define THREADS 256
#define SBLK (CHUNK_PIX / THREADS)       // 7200 scatter work-units / chunk
#define ZBLK (CHUNK_PIX / (2 * THREADS)) // 3600 zero work-units / chunk
#define NBLK (CHUNK_PIX / (2 * THREADS)) // 3600 norm work-units / chunk

#define GRID_BLOCKS (148 * 6)            // 888 co-resident blocks

// Full packed accumulator: (cnt, ox, oy, pad) per pixel.
__device__ float4 g_acc[NPIX];

__device__ __forceinline__ void red_add_v4(float4* addr, float a, float b, float c) {
    asm volatile(
        "red.global.add.v4.f32 [%0], {%1, %2, %3, %4};"
        :: "l"(addr), "f"(a), "f"(b), "f"(c), "f"(0.0f)
        : "memory");
}

// ---------------------------------------------------------------------------
// Role bodies. wu is the role-local work-unit index (one unit = 256 threads
// of work, exactly as one block in the multi-launch version).
// ---------------------------------------------------------------------------
__device__ __forceinline__ void do_scatter(int wu, int chunk,
                                           const float* __restrict__ flow,
                                           const float* __restrict__ depth) {
    int li = wu * THREADS + threadIdx.x;             // [0, CHUNK_PIX)
    int gi = chunk * CHUNK_PIX + li;                 // global pixel

    int b = gi / HW;
    int p = gi - b * HW;
    int y = p / WW;
    int x = p - y * WW;

    const float* fbase = flow + (size_t)b * 2 * HW;
    float fx = __ldcs(fbase + p);
    float fy = __ldcs(fbase + HW + p);
    float d  = __ldcs(depth + gi);

    float x2 = (float)x + fx;
    float y2 = (float)y + fy;

    if (!(x2 >= 0.f && x2 <= (float)(WW - 1) &&
          y2 >= 0.f && y2 <= (float)(HH - 1)))
        return;

    int xL = (int)floorf(x2);
    int yT = (int)floorf(y2);
    int xR = min(xL + 1, WW - 1);
    int yB = min(yT + 1, HH - 1);

    float wx = -fx * d;
    float wy = -fy * d;

    int base = b * HW;
    int rT = base + yT * WW;
    int rB = base + yB * WW;

    red_add_v4(&g_acc[rT + xL], d, wx, wy);
    red_add_v4(&g_acc[rT + xR], d, wx, wy);
    red_add_v4(&g_acc[rB + xL], d, wx, wy);
    red_add_v4(&g_acc[rB + xR], d, wx, wy);
}

__device__ __forceinline__ void do_zero(int wu, int chunk) {
    int t = wu * THREADS + threadIdx.x;              // [0, CHUNK_PIX/2)
    float4 z = make_float4(0.f, 0.f, 0.f, 0.f);
    int base = chunk * CHUNK_PIX;
    g_acc[base + t] = z;
    g_acc[base + t + CHUNK_PIX / 2] = z;
}

__device__ __forceinline__ void do_norm(int wu, int chunk,
                                        float* __restrict__ out) {
    int t = wu * THREADS + threadIdx.x;              // [0, CHUNK_PIX/2)
    int i0 = chunk * CHUNK_PIX + t;
    int i1 = i0 + CHUNK_PIX / 2;

    float4 a0 = g_acc[i0];
    float4 a1 = g_acc[i1];

    float ox0 = 0.f, oy0 = 0.f;
    if (a0.x > 0.f) { float inv = 1.f / a0.x; ox0 = a0.y * inv; oy0 = a0.z * inv; }
    float ox1 = 0.f, oy1 = 0.f;
    if (a1.x > 0.f) { float inv = 1.f / a1.x; ox1 = a1.y * inv; oy1 = a1.z * inv; }

    int b0 = i0 / HW, p0 = i0 - b0 * HW;
    int b1 = i1 / HW, p1 = i1 - b1 * HW;

    float* ob0 = out + (size_t)b0 * 2 * HW;
    float* ob1 = out + (size_t)b1 * 2 * HW;
    __stcs(ob0 + p0,      ox0);
    __stcs(ob0 + HW + p0, oy0);
    __stcs(ob1 + p1,      ox1);
    __stcs(ob1 + HW + p1, oy1);
}

// ---------------------------------------------------------------------------
// Stage executors: grid-stride loops over striped work units (same stripe
// mappings as the multi-launch version).
// ---------------------------------------------------------------------------
__device__ __forceinline__ void stage_Z(int cZ) {
    for (int u = blockIdx.x; u < ZBLK; u += gridDim.x)
        do_zero(u, cZ);
}
__device__ __forceinline__ void stage_SZ(int cS, int cZ,
                                         const float* flow, const float* depth) {
    for (int u = blockIdx.x; u < SBLK + ZBLK; u += gridDim.x) {
        int g = u / 3, r = u - g * 3;
        if (r < 2) do_scatter(g * 2 + r, cS, flow, depth);
        else       do_zero(g, cZ);
    }
}
__device__ __forceinline__ void stage_SZN(int cS, int cZ, int cN,
                                          const float* flow, const float* depth,
                                          float* out) {
    for (int u = blockIdx.x; u < SBLK + ZBLK + NBLK; u += gridDim.x) {
        int g = u >> 2, r = u & 3;
        if (r < 2)       do_scatter(g * 2 + r, cS, flow, depth);
        else if (r == 2) do_zero(g, cZ);
        else             do_norm(g, cN, out);
    }
}
__device__ __forceinline__ void stage_SN(int cS, int cN,
                                         const float* flow, const float* depth,
                                         float* out) {
    for (int u = blockIdx.x; u < SBLK + NBLK; u += gridDim.x) {
        int g = u / 3, r = u - g * 3;
        if (r < 2) do_scatter(g * 2 + r, cS, flow, depth);
        else       do_norm(g, cN, out);
    }
}
__device__ __forceinline__ void stage_N(int cN, float* out) {
    for (int u = blockIdx.x; u < NBLK; u += gridDim.x)
        do_norm(u, cN, out);
}

// ---------------------------------------------------------------------------
// Single persistent cooperative kernel: 6 pipeline stages separated by
// grid.sync() instead of kernel boundaries.
// ---------------------------------------------------------------------------
__global__ void __launch_bounds__(THREADS, 6)
persistent_kernel(const float* __restrict__ flow,
                  const float* __restrict__ depth,
                  float* __restrict__ out) {
    cg::grid_group grid = cg::this_grid();

    stage_Z(0);                          // Z0
    grid.sync();
    stage_SZ(0, 1, flow, depth);         // S0 + Z1
    grid.sync();
    stage_SZN(1, 2, 0, flow, depth, out); // S1 + Z2 + N0
    grid.sync();
    stage_SZN(2, 3, 1, flow, depth, out); // S2 + Z3 + N1
    grid.sync();
    stage_SN(3, 2, flow, depth, out);    // S3 + N2
    grid.sync();
    stage_N(3, out);                     // N3
}

extern "C" void kernel_launch(void* const* d_in, const int* in_sizes, int n_in,
                              void* d_out, int out_size) {
    const float* flow  = (const float*)d_in[0];   // (B, 2, H, W)
    const float* depth = (const float*)d_in[1];   // (B, 1, H, W)
    float* out = (float*)d_out;                   // (B, 2, H, W)

    (void)in_sizes; (void)n_in; (void)out_size;

    void* args[] = { (void*)&flow, (void*)&depth, (void*)&out };
    cudaLaunchCooperativeKernel((void*)persistent_kernel,
                                dim3(GRID_BLOCKS), dim3(THREADS),
                                args, 0, (cudaStream_t)0);
}

// round 14
// speedup vs baseline: 1.4472x; 1.4472x over previous
#include <cuda_runtime.h>
#include <math.h>

#define BATCH 8
#define HH 720
#define WW 1280
#define HW (HH * WW)
#define NPIX (BATCH * HW)

#define CB 2                       // batches per chunk
#define NCHUNK (BATCH / CB)        // 4 independent chains
#define CHUNK_PIX (CB * HW)        // 1,843,200

#define THREADS 256
#define SBLK (CHUNK_PIX / THREADS)       // 7200 scatter blocks / chunk
#define ZBLK (CHUNK_PIX / (2 * THREADS)) // 3600 zero blocks / chunk
#define NBLK (CHUNK_PIX / (2 * THREADS)) // 3600 norm blocks / chunk

// Full packed accumulator: (cnt, ox, oy, pad) per pixel.
__device__ float4 g_acc[NPIX];

__device__ __forceinline__ void red_add_v4(float4* addr, float a, float b, float c) {
    asm volatile(
        "red.global.add.v4.f32 [%0], {%1, %2, %3, %4};"
        :: "l"(addr), "f"(a), "f"(b), "f"(c), "f"(0.0f)
        : "memory");
}

// ---------------------------------------------------------------------------
// Per-chunk kernels (round-9 proven bodies).
// ---------------------------------------------------------------------------
__global__ void zero_kernel(int chunk) {
    int t = blockIdx.x * blockDim.x + threadIdx.x;   // [0, CHUNK_PIX/2)
    float4 z = make_float4(0.f, 0.f, 0.f, 0.f);
    int base = chunk * CHUNK_PIX;
    g_acc[base + t] = z;
    g_acc[base + t + CHUNK_PIX / 2] = z;
}

__global__ void scatter_kernel(const float* __restrict__ flow,
                               const float* __restrict__ depth,
                               int chunk) {
    int li = blockIdx.x * blockDim.x + threadIdx.x;  // [0, CHUNK_PIX)
    int gi = chunk * CHUNK_PIX + li;                 // global pixel

    int b = gi / HW;
    int p = gi - b * HW;
    int y = p / WW;
    int x = p - y * WW;

    const float* fbase = flow + (size_t)b * 2 * HW;
    float fx = __ldcs(fbase + p);
    float fy = __ldcs(fbase + HW + p);
    float d  = __ldcs(depth + gi);

    float x2 = (float)x + fx;
    float y2 = (float)y + fy;

    if (!(x2 >= 0.f && x2 <= (float)(WW - 1) &&
          y2 >= 0.f && y2 <= (float)(HH - 1)))
        return;

    int xL = (int)floorf(x2);
    int yT = (int)floorf(y2);
    int xR = min(xL + 1, WW - 1);
    int yB = min(yT + 1, HH - 1);

    float wx = -fx * d;
    float wy = -fy * d;

    int base = b * HW;
    int rT = base + yT * WW;
    int rB = base + yB * WW;

    red_add_v4(&g_acc[rT + xL], d, wx, wy);
    red_add_v4(&g_acc[rT + xR], d, wx, wy);
    red_add_v4(&g_acc[rB + xL], d, wx, wy);
    red_add_v4(&g_acc[rB + xR], d, wx, wy);
}

__global__ void normalize_kernel(float* __restrict__ out, int chunk) {
    int t = blockIdx.x * blockDim.x + threadIdx.x;   // [0, CHUNK_PIX/2)
    int i0 = chunk * CHUNK_PIX + t;
    int i1 = i0 + CHUNK_PIX / 2;

    float4 a0 = g_acc[i0];
    float4 a1 = g_acc[i1];

    float ox0 = 0.f, oy0 = 0.f;
    if (a0.x > 0.f) { float inv = 1.f / a0.x; ox0 = a0.y * inv; oy0 = a0.z * inv; }
    float ox1 = 0.f, oy1 = 0.f;
    if (a1.x > 0.f) { float inv = 1.f / a1.x; ox1 = a1.y * inv; oy1 = a1.z * inv; }

    int b0 = i0 / HW, p0 = i0 - b0 * HW;
    int b1 = i1 / HW, p1 = i1 - b1 * HW;

    float* ob0 = out + (size_t)b0 * 2 * HW;
    float* ob1 = out + (size_t)b1 * 2 * HW;
    __stcs(ob0 + p0,      ox0);
    __stcs(ob0 + HW + p0, oy0);
    __stcs(ob1 + p1,      ox1);
    __stcs(ob1 + HW + p1, oy1);
}

// ---------------------------------------------------------------------------
// Launch: 4 independent Z->S->N chains on forked capture streams. The graph
// records the true DAG; the block scheduler overlaps chains, eliminating
// stage-boundary drain.
// ---------------------------------------------------------------------------
extern "C" void kernel_launch(void* const* d_in, const int* in_sizes, int n_in,
                              void* d_out, int out_size) {
    const float* flow  = (const float*)d_in[0];   // (B, 2, H, W)
    const float* depth = (const float*)d_in[1];   // (B, 1, H, W)
    float* out = (float*)d_out;                   // (B, 2, H, W)

    (void)in_sizes; (void)n_in; (void)out_size;

    cudaStream_t s[NCHUNK];
    cudaEvent_t  done[NCHUNK];
    cudaEvent_t  root;

    cudaEventCreateWithFlags(&root, cudaEventDisableTiming);
    cudaEventRecord(root, 0);                     // fork point on capture stream

    for (int c = 0; c < NCHUNK; c++) {
        cudaStreamCreateWithFlags(&s[c], cudaStreamNonBlocking);
        cudaStreamWaitEvent(s[c], root, 0);

        zero_kernel<<<ZBLK, THREADS, 0, s[c]>>>(c);
        scatter_kernel<<<SBLK, THREADS, 0, s[c]>>>(flow, depth, c);
        normalize_kernel<<<NBLK, THREADS, 0, s[c]>>>(out, c);

        cudaEventCreateWithFlags(&done[c], cudaEventDisableTiming);
        cudaEventRecord(done[c], s[c]);
        cudaStreamWaitEvent(0, done[c], 0);       // join back to capture stream
    }

    for (int c = 0; c < NCHUNK; c++) {
        cudaStreamDestroy(s[c]);
        cudaEventDestroy(done[c]);
    }
    cudaEventDestroy(root);
}

// round 15
// speedup vs baseline: 1.6250x; 1.1229x over previous
#include <cuda_runtime.h>
#include <math.h>

#define BATCH 8
#define HH 720
#define WW 1280
#define HW (HH * WW)
#define NPIX (BATCH * HW)

#define QH (HH / 2)            // 360 quad rows per parity plane
#define QW (WW / 2)            // 640 quad cols per parity plane
#define PLANE (QH * QW)        // 230,400 entries per parity plane
#define NQUAD (BATCH * 4 * PLANE)  // 7,372,800 entries total (118 MB)

// Quad accumulator: entry (b, py, px, qy, qx) accumulates (cnt, ox, oy, pad)
// destined for the 2x2 pixel block rows {2qy+py, 2qy+py+1} x cols {2qx+px, 2qx+px+1}.
__device__ float4 g_quad[NQUAD];

__device__ __forceinline__ void red_add_v4(float4* addr, float a, float b, float c) {
    asm volatile(
        "red.global.add.v4.f32 [%0], {%1, %2, %3, %4};"
        :: "l"(addr), "f"(a), "f"(b), "f"(c), "f"(0.0f)
        : "memory");
}

// ---------------------------------------------------------------------------
// Kernel 1: zero the quad accumulator (coalesced float4 stores, grid-stride).
// ---------------------------------------------------------------------------
__global__ void zero_kernel() {
    float4 z = make_float4(0.f, 0.f, 0.f, 0.f);
    int stride = gridDim.x * blockDim.x;
    for (int k = blockIdx.x * blockDim.x + threadIdx.x; k < NQUAD; k += stride) {
        g_quad[k] = z;
    }
}

// ---------------------------------------------------------------------------
// Kernel 2: scatter. ONE vector reduction per valid source pixel: all four
// bilinear corners receive identical (d, wx, wy), so we add once to the
// anchor's quad entry. Exact-boundary clamps (x2 == W-1 / y2 == H-1) double
// the contribution per clamped axis; the phantom row/col of the 2x2 block
// is never read by normalize.
// ---------------------------------------------------------------------------
__global__ void scatter_kernel(const float* __restrict__ flow,
                               const float* __restrict__ depth) {
    int i = blockIdx.x * blockDim.x + threadIdx.x;
    if (i >= NPIX) return;

    int b = i / HW;
    int p = i - b * HW;
    int y = p / WW;
    int x = p - y * WW;

    const float* fbase = flow + (size_t)b * 2 * HW;
    float fx = __ldcs(fbase + p);
    float fy = __ldcs(fbase + HW + p);
    float d  = __ldcs(depth + i);

    float x2 = (float)x + fx;
    float y2 = (float)y + fy;

    if (!(x2 >= 0.f && x2 <= (float)(WW - 1) &&
          y2 >= 0.f && y2 <= (float)(HH - 1)))
        return;

    int xL = (int)floorf(x2);
    int yT = (int)floorf(y2);

    float s = 1.f;
    if (xL == WW - 1) s *= 2.f;   // x-clamp: both corners coincide
    if (yT == HH - 1) s *= 2.f;   // y-clamp: both rows coincide

    float wx = -fx * d;
    float wy = -fy * d;

    int idx = ((b * 4 + (yT & 1) * 2 + (xL & 1)) * QH + (yT >> 1)) * QW + (xL >> 1);
    red_add_v4(&g_quad[idx], s * d, s * wx, s * wy);
}

// ---------------------------------------------------------------------------
// Kernel 3: gather-normalize. Pixel (y,x) sums the <=4 anchor entries whose
// 2x2 block covers it: anchors (sy, sx) in {y-1, y} x {x-1, x} (each parity
// plane contributes at most one entry). Then divide and write (B,2,H,W).
// ---------------------------------------------------------------------------
__global__ void normalize_kernel(float* __restrict__ out) {
    int i = blockIdx.x * blockDim.x + threadIdx.x;
    if (i >= NPIX) return;

    int b = i / HW;
    int p = i - b * HW;
    int y = p / WW;
    int x = p - y * WW;

    float cnt = 0.f, sox = 0.f, soy = 0.f;

#pragma unroll
    for (int ky = 0; ky < 2; ky++) {
        int sy = y - ky;
        if (sy < 0) continue;
        int py = sy & 1, qy = sy >> 1;
#pragma unroll
        for (int kx = 0; kx < 2; kx++) {
            int sx = x - kx;
            if (sx < 0) continue;
            int px = sx & 1, qx = sx >> 1;
            float4 a = g_quad[((b * 4 + py * 2 + px) * QH + qy) * QW + qx];
            cnt += a.x; sox += a.y; soy += a.z;
        }
    }

    float ox = 0.f, oy = 0.f;
    if (cnt > 0.f) {
        float inv = 1.f / cnt;
        ox = sox * inv;
        oy = soy * inv;
    }

    float* obase = out + (size_t)b * 2 * HW;
    __stcs(obase + p,      ox);
    __stcs(obase + HW + p, oy);
}

extern "C" void kernel_launch(void* const* d_in, const int* in_sizes, int n_in,
                              void* d_out, int out_size) {
    const float* flow  = (const float*)d_in[0];   // (B, 2, H, W)
    const float* depth = (const float*)d_in[1];   // (B, 1, H, W)
    float* out = (float*)d_out;                   // (B, 2, H, W)

    (void)in_sizes; (void)n_in; (void)out_size;

    const int threads = 256;

    zero_kernel<<<1480, threads>>>();

    int blocks = (NPIX + threads - 1) / threads;  // 28800
    scatter_kernel<<<blocks, threads>>>(flow, depth);
    normalize_kernel<<<blocks, threads>>>(out);
}

// round 16
// speedup vs baseline: 2.3104x; 1.4218x over previous
#include <cuda_runtime.h>
#include <math.h>

#define BATCH 8
#define HH 720
#define WW 1280
#define HW (HH * WW)
#define NPIX (BATCH * HW)

#define QH (HH / 2)            // 360 quad rows per parity plane
#define QW (WW / 2)            // 640 quad cols per parity plane
#define PLANE (QH * QW)        // 230,400 entries per parity plane
#define NQUAD (BATCH * 4 * PLANE)  // 7,372,800 entries (118 MB)

// Quad accumulator: entry (b, py, px, qy, qx) accumulates (cnt, ox, oy, pad)
// destined for the 2x2 pixel block rows {2qy+py, 2qy+py+1} x cols {2qx+px, 2qx+px+1}.
__device__ float4 g_quad[NQUAD];

__device__ __forceinline__ void red_add_v4(float4* addr, float a, float b, float c) {
    asm volatile(
        "red.global.add.v4.f32 [%0], {%1, %2, %3, %4};"
        :: "l"(addr), "f"(a), "f"(b), "f"(c), "f"(0.0f)
        : "memory");
}

// ---------------------------------------------------------------------------
// Kernel 1: zero the quad accumulator (coalesced float4 stores, grid-stride).
// ---------------------------------------------------------------------------
__global__ void zero_kernel() {
    float4 z = make_float4(0.f, 0.f, 0.f, 0.f);
    int stride = gridDim.x * blockDim.x;
    for (int k = blockIdx.x * blockDim.x + threadIdx.x; k < NQUAD; k += stride) {
        g_quad[k] = z;
    }
}

// ---------------------------------------------------------------------------
// Kernel 2: scatter. ONE vector reduction per valid source pixel (all four
// bilinear corners receive identical values; exact-boundary clamps double
// the contribution per clamped axis; phantom row/col never read).
// ---------------------------------------------------------------------------
__global__ void scatter_kernel(const float* __restrict__ flow,
                               const float* __restrict__ depth) {
    int i = blockIdx.x * blockDim.x + threadIdx.x;
    if (i >= NPIX) return;

    int b = i / HW;
    int p = i - b * HW;
    int y = p / WW;
    int x = p - y * WW;

    const float* fbase = flow + (size_t)b * 2 * HW;
    float fx = __ldcs(fbase + p);
    float fy = __ldcs(fbase + HW + p);
    float d  = __ldcs(depth + i);

    float x2 = (float)x + fx;
    float y2 = (float)y + fy;

    if (!(x2 >= 0.f && x2 <= (float)(WW - 1) &&
          y2 >= 0.f && y2 <= (float)(HH - 1)))
        return;

    int xL = (int)floorf(x2);
    int yT = (int)floorf(y2);

    float s = 1.f;
    if (xL == WW - 1) s *= 2.f;   // x-clamp: both corners coincide
    if (yT == HH - 1) s *= 2.f;   // y-clamp: both rows coincide

    float wx = -fx * d;
    float wy = -fy * d;

    int idx = ((b * 4 + (yT & 1) * 2 + (xL & 1)) * QH + (yT >> 1)) * QW + (xL >> 1);
    red_add_v4(&g_quad[idx], s * d, s * wx, s * wy);
}

// ---------------------------------------------------------------------------
// Kernel 3: block-gather normalize. One thread produces the 2x2 output block
// (2Y..2Y+1, 2X..2X+1) from the 9 covering anchors; shared anchors reused in
// registers. 9 LDG.128 + 4 STG.64 per 4 pixels.
// ---------------------------------------------------------------------------
__global__ void normalize_kernel(float* __restrict__ out) {
    int t = blockIdx.x * blockDim.x + threadIdx.x;   // [0, BATCH*PLANE)
    int b = t / PLANE;
    int r = t - b * PLANE;
    int Y = r / QW;
    int X = r - Y * QW;

    const float4* pl00 = g_quad + (size_t)(b * 4 + 0) * PLANE; // py0 px0
    const float4* pl01 = g_quad + (size_t)(b * 4 + 1) * PLANE; // py0 px1
    const float4* pl10 = g_quad + (size_t)(b * 4 + 2) * PLANE; // py1 px0
    const float4* pl11 = g_quad + (size_t)(b * 4 + 3) * PLANE; // py1 px1

    // Per-pixel sums: index dy*2+dx.
    float cnt[4] = {0.f, 0.f, 0.f, 0.f};
    float sox[4] = {0.f, 0.f, 0.f, 0.f};
    float soy[4] = {0.f, 0.f, 0.f, 0.f};

#define ADDP(A, pix) { cnt[pix] += (A).x; sox[pix] += (A).y; soy[pix] += (A).z; }

    int row  = Y * QW + X;
    int rowm = row - QW;   // (Y-1)*QW + X

    // r = -1 anchors (sy = 2Y-1): feed pixel row 0 only.
    if (Y > 0) {
        if (X > 0) { float4 a = pl11[rowm - 1]; ADDP(a, 0); }          // A(-1,-1) -> (0,0)
        { float4 a = pl10[rowm]; ADDP(a, 0); ADDP(a, 1); }             // A(-1,0) -> (0,0),(0,1)
        { float4 a = pl11[rowm]; ADDP(a, 1); }                         // A(-1,1) -> (0,1)
    }
    // r = 0 anchors (sy = 2Y): feed both pixel rows.
    if (X > 0) { float4 a = pl01[row - 1]; ADDP(a, 0); ADDP(a, 2); }   // A(0,-1)
    { float4 a = pl00[row]; ADDP(a, 0); ADDP(a, 1); ADDP(a, 2); ADDP(a, 3); } // A(0,0)
    { float4 a = pl01[row]; ADDP(a, 1); ADDP(a, 3); }                 // A(0,1)
    // r = +1 anchors (sy = 2Y+1): feed pixel row 1 only.
    if (X > 0) { float4 a = pl11[row - 1]; ADDP(a, 2); }               // A(1,-1)
    { float4 a = pl10[row]; ADDP(a, 2); ADDP(a, 3); }                 // A(1,0)
    { float4 a = pl11[row]; ADDP(a, 3); }                             // A(1,1)
#undef ADDP

    float ox[4], oy[4];
#pragma unroll
    for (int k = 0; k < 4; k++) {
        ox[k] = 0.f; oy[k] = 0.f;
        if (cnt[k] > 0.f) {
            float inv = 1.f / cnt[k];
            ox[k] = sox[k] * inv;
            oy[k] = soy[k] * inv;
        }
    }

    int y0 = 2 * Y, x0 = 2 * X;
    float* obase = out + (size_t)b * 2 * HW;
    float* orow0 = obase + y0 * WW + x0;
    float* orow1 = orow0 + WW;

    __stcs(reinterpret_cast<float2*>(orow0),      make_float2(ox[0], ox[1]));
    __stcs(reinterpret_cast<float2*>(orow1),      make_float2(ox[2], ox[3]));
    __stcs(reinterpret_cast<float2*>(orow0 + HW), make_float2(oy[0], oy[1]));
    __stcs(reinterpret_cast<float2*>(orow1 + HW), make_float2(oy[2], oy[3]));
}

extern "C" void kernel_launch(void* const* d_in, const int* in_sizes, int n_in,
                              void* d_out, int out_size) {
    const float* flow  = (const float*)d_in[0];   // (B, 2, H, W)
    const float* depth = (const float*)d_in[1];   // (B, 1, H, W)
    float* out = (float*)d_out;                   // (B, 2, H, W)

    (void)in_sizes; (void)n_in; (void)out_size;

    const int threads = 256;

    zero_kernel<<<1480, threads>>>();

    int blocks = (NPIX + threads - 1) / threads;  // 28800
    scatter_kernel<<<blocks, threads>>>(flow, depth);

    int nblocks = (BATCH * PLANE) / threads;      // 7200
    normalize_kernel<<<nblocks, threads>>>(out);
}